// round 5
// baseline (speedup 1.0000x reference)
#include <cuda_runtime.h>
#include <math.h>

// Row-normalize: out[r, c] = in[r, c] / sum_c in[r, c]
// 65536 rows of 1024 floats. One WARP per row.
// Row staged in SMEM via cp.async.cg (LDGSTS, L1-bypass):
//   - 8x 16B cp.async per lane (MLP=8, no registers held)
//   - sum from smem (each lane reads only what it wrote -> no barrier)
//   - warp-shuffle reduce, inv with nan/inf guard
//   - reload from smem, scale, STG.128
// Low register count -> high occupancy -> saturate HBM.

static constexpr int ROW_LEN     = 1024;
static constexpr int V4_PER_ROW  = ROW_LEN / 4;   // 256 float4 per row
static constexpr int V4_PER_LANE = 8;             // per lane
static constexpr int THREADS     = 256;
static constexpr int WARPS       = THREADS / 32;  // 8 warps -> 32 KB smem/CTA

__global__ __launch_bounds__(THREADS)
void normalizer_kernel(const float* __restrict__ in, float* __restrict__ out) {
    __shared__ float4 buf[WARPS * V4_PER_ROW];    // 8 * 256 * 16B = 32 KB

    const int lane = threadIdx.x & 31;
    const int wid  = threadIdx.x >> 5;
    const long long row = (long long)blockIdx.x * WARPS + wid;

    const float4* in4  = reinterpret_cast<const float4*>(in)  + row * V4_PER_ROW + lane;
    float4*       out4 = reinterpret_cast<float4*>(out)       + row * V4_PER_ROW + lane;

    float4* mybuf = buf + wid * V4_PER_ROW + lane;
    unsigned saddr = (unsigned)__cvta_generic_to_shared(mybuf);

    // Deep async pipeline: 8 x LDGSTS.16B per lane, L1-bypass.
    #pragma unroll
    for (int i = 0; i < V4_PER_LANE; i++) {
        asm volatile("cp.async.cg.shared.global [%0], [%1], 16;\n"
                     :: "r"(saddr + i * 32 * 16), "l"(in4 + i * 32));
    }
    asm volatile("cp.async.commit_group;\n");
    asm volatile("cp.async.wait_group 0;\n" ::: "memory");

    // Each lane sums exactly the elements it copied itself -> no barrier needed.
    float s = 0.0f;
    #pragma unroll
    for (int i = 0; i < V4_PER_LANE; i++) {
        float4 v = mybuf[i * 32];
        s += (v.x + v.y) + (v.z + v.w);
    }

    #pragma unroll
    for (int off = 16; off > 0; off >>= 1)
        s += __shfl_xor_sync(0xFFFFFFFFu, s, off);

    float inv = 1.0f / s;
    inv = isfinite(inv) ? inv : 0.0f;

    // Compiler barrier: force phase 2 to re-read smem instead of keeping
    // all 32 floats live in registers (keeps regs low -> occupancy high).
    asm volatile("" ::: "memory");

    #pragma unroll
    for (int i = 0; i < V4_PER_LANE; i++) {
        float4 v = mybuf[i * 32];
        v.x *= inv; v.y *= inv; v.z *= inv; v.w *= inv;
        out4[i * 32] = v;
    }
}

extern "C" void kernel_launch(void* const* d_in, const int* in_sizes, int n_in,
                              void* d_out, int out_size) {
    const float* adj = (const float*)d_in[0];
    float* out = (float*)d_out;
    const long long total = (long long)in_sizes[0];      // 2*32*1024*1024
    const int n_rows = (int)(total / ROW_LEN);            // 65536
    const int n_blocks = n_rows / WARPS;                  // 8192
    normalizer_kernel<<<n_blocks, THREADS>>>(adj, out);
}

// round 7
// speedup vs baseline: 1.0020x; 1.0020x over previous
#include <cuda_runtime.h>
#include <math.h>

// Row-normalize: out[r, c] = in[r, c] / sum_c in[r, c]
// 65536 rows of 1024 floats. One WARP per row:
//   8x float4 streaming loads (__ldcs, evict-first: input is read-once),
//   warp-shuffle reduce, scale, 8x float4 streaming stores (__stcs).
// Pure streaming workload -> keep L2 out of the way.

static constexpr int ROW_LEN     = 1024;
static constexpr int V4_PER_ROW  = ROW_LEN / 4;     // 256 float4 per row
static constexpr int V4_PER_LANE = V4_PER_ROW / 32; // 8 float4 per lane
static constexpr int THREADS     = 256;             // 8 warps per CTA
static constexpr int WARPS       = THREADS / 32;

__global__ __launch_bounds__(THREADS)
void normalizer_kernel(const float* __restrict__ in, float* __restrict__ out) {
    const int lane = threadIdx.x & 31;
    const int wid  = threadIdx.x >> 5;
    const long long row   = (long long)blockIdx.x * WARPS + wid;  // 0 .. 65535
    const long long base4 = row * V4_PER_ROW;

    const float4* in4  = reinterpret_cast<const float4*>(in)  + base4 + lane;
    float4*       out4 = reinterpret_cast<float4*>(out)       + base4 + lane;

    // Front-batched streaming loads: 8 independent LDG.E.128.CS in flight.
    float4 v[V4_PER_LANE];
    #pragma unroll
    for (int i = 0; i < V4_PER_LANE; i++)
        v[i] = __ldcs(in4 + i * 32);

    float s = 0.0f;
    #pragma unroll
    for (int i = 0; i < V4_PER_LANE; i++)
        s += (v[i].x + v[i].y) + (v[i].z + v[i].w);

    #pragma unroll
    for (int off = 16; off > 0; off >>= 1)
        s += __shfl_xor_sync(0xFFFFFFFFu, s, off);

    float inv = 1.0f / s;
    inv = isfinite(inv) ? inv : 0.0f;

    #pragma unroll
    for (int i = 0; i < V4_PER_LANE; i++) {
        float4 r;
        r.x = v[i].x * inv;
        r.y = v[i].y * inv;
        r.z = v[i].z * inv;
        r.w = v[i].w * inv;
        __stcs(out4 + i * 32, r);   // STG.E.128 streaming (evict-first)
    }
}

extern "C" void kernel_launch(void* const* d_in, const int* in_sizes, int n_in,
                              void* d_out, int out_size) {
    const float* adj = (const float*)d_in[0];
    float* out = (float*)d_out;
    const long long total = (long long)in_sizes[0];      // 2*32*1024*1024
    const int n_rows = (int)(total / ROW_LEN);            // 65536
    const int n_blocks = n_rows / WARPS;                  // 8192
    normalizer_kernel<<<n_blocks, THREADS>>>(adj, out);
}